// round 8
// baseline (speedup 1.0000x reference)
#include <cuda_runtime.h>
#include <cuda_bf16.h>
#include <cstdint>

// Problem constants
#define BSZ    2
#define LSEQ   1024
#define DMODEL 1024
#define NH     16
#define DH     64
#define WWIN   64
#define MTOT   (BSZ * LSEQ)      // 2048

// ---------------------------------------------------------------------------
// Scratch (device globals — no allocation allowed)
// ---------------------------------------------------------------------------
__device__ float g_xr  [MTOT * DMODEL];         // x rounded to tf32
__device__ float g_wr  [3 * DMODEL * DMODEL];   // Wq|Wk|Wv rows stacked, tf32-rounded
__device__ float g_wor [DMODEL * DMODEL];       // Wo tf32-rounded
__device__ float g_attr[MTOT * DMODEL];         // attention out, tf32-rounded
__device__ float g_qkv [MTOT * 3 * DMODEL];     // q|k|v f32, row-concat

// ---------------------------------------------------------------------------
// helpers
// ---------------------------------------------------------------------------
__device__ __forceinline__ uint32_t smem_u32(const void* p) {
    uint32_t a;
    asm("{ .reg .u64 t; cvta.to.shared.u64 t, %1; cvt.u32.u64 %0, t; }" : "=r"(a) : "l"(p));
    return a;
}
__device__ __forceinline__ float tf32_round(float v) {
    uint32_t o;
    asm("cvt.rna.tf32.f32 %0, %1;" : "=r"(o) : "f"(v));
    return __uint_as_float(o);
}
#define CP_ASYNC16(dst, src) \
    asm volatile("cp.async.cg.shared.global [%0], [%1], 16;" :: "r"(dst), "l"(src) : "memory")
#define CP_ASYNC_COMMIT() asm volatile("cp.async.commit_group;" ::: "memory")
#define CP_ASYNC_WAIT(n)  asm volatile("cp.async.wait_group %0;" :: "n"(n) : "memory")

__device__ __forceinline__ void mma_tf32(float* c, uint32_t a0, uint32_t a1,
                                         uint32_t a2, uint32_t a3,
                                         uint32_t b0, uint32_t b1) {
    asm volatile(
        "mma.sync.aligned.m16n8k8.row.col.f32.tf32.tf32.f32 "
        "{%0,%1,%2,%3}, {%4,%5,%6,%7}, {%8,%9}, {%0,%1,%2,%3};"
        : "+f"(c[0]), "+f"(c[1]), "+f"(c[2]), "+f"(c[3])
        : "r"(a0), "r"(a1), "r"(a2), "r"(a3), "r"(b0), "r"(b1));
}
__device__ __forceinline__ void ldsm4(uint32_t& r0, uint32_t& r1, uint32_t& r2,
                                      uint32_t& r3, uint32_t addr) {
    asm volatile("ldmatrix.sync.aligned.m8n8.x4.shared.b16 {%0,%1,%2,%3}, [%4];"
                 : "=r"(r0), "=r"(r1), "=r"(r2), "=r"(r3) : "r"(addr));
}

// ---------------------------------------------------------------------------
// TF32 tensor-core GEMM: C[M][Ntot] = A[M][1024] @ B[Ntot][1024]^T
// CTA 128x128, BK=32, 4 warps with 64x64 warp tiles (32 MMAs per fragment
// set -> long independent HMMA bursts), 3-stage cp.async pipeline,
// ldmatrix fragment loads. 2 CTAs/SM.
// ---------------------------------------------------------------------------
#define BK 32
#define NST (DMODEL / BK)             // 32 stages
#define SROW 36                       // padded row, words
#define TILE_WORDS (128 * SROW)       // per matrix per stage
#define TILE_BYTES (TILE_WORDS * 4)
#define STAGE_WORDS (2 * TILE_WORDS)  // A + B
#define STAGE_BYTES (STAGE_WORDS * 4)
#define GEMM_SMEM_BYTES (3 * STAGE_BYTES)  // 110592

__global__ __launch_bounds__(128, 2) void gemm_tf32_kernel(
    const float* __restrict__ A, const float* __restrict__ B,
    float* __restrict__ C, int Ntot)
{
    extern __shared__ float smem[];
    const int tid  = threadIdx.x;
    const int wid  = tid >> 5;
    const int lane = tid & 31;
    const int bn = blockIdx.x * 128;
    const int bm = blockIdx.y * 128;

    const int wm = (wid & 1) * 64;    // warp m offset (2 warps over 128 rows)
    const int wn = (wid >> 1) * 64;   // warp n offset (2 warps over 128 cols)
    const int qr = lane >> 2;
    const int qc = lane & 3;

    const uint32_t smem_base = smem_u32(smem);
    const float* gA = A + (size_t)bm * DMODEL;
    const float* gB = B + (size_t)bn * DMODEL;

    // ldmatrix per-lane byte offsets within a stage tile
    // A (x4): tiles = [rows 0-7,k0][rows 8-15,k0][rows 0-7,k0+4][rows 8-15,k0+4]
    const int a_row = ((lane >> 3) & 1) * 8 + (lane & 7);
    const int a_ko  = (lane >> 4) * 4;
    uint32_t offA[4];
    #pragma unroll
    for (int mi = 0; mi < 4; mi++)
        offA[mi] = (uint32_t)(((wm + mi * 16 + a_row) * SROW + a_ko) * 4);
    // B (x4): tiles = [n 0-7,k0][n 0-7,k0+4][n 8-15,k0][n 8-15,k0+4] per ni-pair
    const int b_row = (lane >> 4) * 8 + (lane & 7);
    const int b_ko  = ((lane >> 3) & 1) * 4;
    uint32_t offB[4];
    #pragma unroll
    for (int p = 0; p < 4; p++)
        offB[p] = (uint32_t)(TILE_BYTES + ((wn + p * 16 + b_row) * SROW + b_ko) * 4);

    auto load_stage = [&](int s) {
        uint32_t dst = smem_base + (uint32_t)(s % 3) * STAGE_BYTES;
        uint32_t dstB = dst + TILE_BYTES;
        const float* pA = gA + s * BK;
        const float* pB = gB + s * BK;
        #pragma unroll
        for (int i = 0; i < 8; i++) {
            int id = tid + i * 128;       // 0..1023
            int row = id >> 3;
            int ch  = id & 7;
            uint32_t so = (uint32_t)(row * SROW + ch * 4) * 4;
            CP_ASYNC16(dst  + so, pA + (size_t)row * DMODEL + ch * 4);
            CP_ASYNC16(dstB + so, pB + (size_t)row * DMODEL + ch * 4);
        }
    };

    float acc[4][8][4];
    #pragma unroll
    for (int mi = 0; mi < 4; mi++)
        #pragma unroll
        for (int ni = 0; ni < 8; ni++)
            #pragma unroll
            for (int j = 0; j < 4; j++) acc[mi][ni][j] = 0.0f;

    load_stage(0); CP_ASYNC_COMMIT();
    load_stage(1); CP_ASYNC_COMMIT();

    for (int s = 0; s < NST; s++) {
        CP_ASYNC_WAIT(1);            // stage s resident
        __syncthreads();             // all warps done with buffer being refilled
        if (s + 2 < NST) load_stage(s + 2);
        CP_ASYNC_COMMIT();

        const uint32_t stage = smem_base + (uint32_t)(s % 3) * STAGE_BYTES;

        #pragma unroll
        for (int ks = 0; ks < 4; ks++) {
            const uint32_t kb = (uint32_t)(ks * 32);  // 8 words
            uint32_t af[4][4];
            #pragma unroll
            for (int mi = 0; mi < 4; mi++)
                ldsm4(af[mi][0], af[mi][1], af[mi][2], af[mi][3], stage + offA[mi] + kb);
            uint32_t bf[8][2];
            #pragma unroll
            for (int p = 0; p < 4; p++)
                ldsm4(bf[2*p][0], bf[2*p][1], bf[2*p+1][0], bf[2*p+1][1],
                      stage + offB[p] + kb);
            #pragma unroll
            for (int mi = 0; mi < 4; mi++)
                #pragma unroll
                for (int ni = 0; ni < 8; ni++)
                    mma_tf32(acc[mi][ni], af[mi][0], af[mi][1], af[mi][2], af[mi][3],
                             bf[ni][0], bf[ni][1]);
        }
    }

    // epilogue: direct global stores
    #pragma unroll
    for (int mi = 0; mi < 4; mi++) {
        const int row = bm + wm + mi * 16 + qr;
        #pragma unroll
        for (int ni = 0; ni < 8; ni++) {
            const int col = bn + wn + ni * 8 + qc * 2;
            float* p0 = C + (size_t)row * Ntot + col;
            float* p1 = p0 + (size_t)8 * Ntot;
            *(float2*)p0 = make_float2(acc[mi][ni][0], acc[mi][ni][1]);
            *(float2*)p1 = make_float2(acc[mi][ni][2], acc[mi][ni][3]);
        }
    }
}

// ---------------------------------------------------------------------------
// tf32 rounding prepasses
// ---------------------------------------------------------------------------
__global__ __launch_bounds__(256) void round_kernel(
    const float* __restrict__ src, float* __restrict__ dst, int n4)
{
    int i = blockIdx.x * 256 + threadIdx.x;
    if (i >= n4) return;
    float4 v = ((const float4*)src)[i];
    v.x = tf32_round(v.x); v.y = tf32_round(v.y);
    v.z = tf32_round(v.z); v.w = tf32_round(v.w);
    ((float4*)dst)[i] = v;
}

__global__ __launch_bounds__(256) void round_w3_kernel(
    const float* __restrict__ Wq, const float* __restrict__ Wk,
    const float* __restrict__ Wv, float* __restrict__ dst)
{
    int i = blockIdx.x * 256 + threadIdx.x;
    int n4 = 3 * DMODEL * DMODEL / 4;
    if (i >= n4) return;
    int seg = i / (DMODEL * DMODEL / 4);
    int off = i - seg * (DMODEL * DMODEL / 4);
    const float* W = (seg == 0) ? Wq : ((seg == 1) ? Wk : Wv);
    float4 v = ((const float4*)W)[off];
    v.x = tf32_round(v.x); v.y = tf32_round(v.y);
    v.z = tf32_round(v.z); v.w = tf32_round(v.w);
    ((float4*)dst)[i] = v;
}

// ---------------------------------------------------------------------------
// Band attention (fp32 math, shuffle softmax). Reads q|k|v from g_qkv;
// writes tf32-rounded output directly to g_attr (out-proj input).
// ---------------------------------------------------------------------------
#define KV_STRIDE 68
#define S_STRIDE  66
#define QKV_LD    (3 * DMODEL)

__global__ __launch_bounds__(256) void band_attn_kernel(
    const float* __restrict__ last_k, const float* __restrict__ last_v)
{
    extern __shared__ float smem[];
    float* sK = smem;
    float* sV = sK + 127 * KV_STRIDE;
    float* sQ = sV + 127 * KV_STRIDE;
    float* sS = sQ + 64 * KV_STRIDE;

    const int l0 = blockIdx.x * 64;
    const int h  = blockIdx.y;
    const int b  = blockIdx.z;
    const int tid = threadIdx.x;

    for (int idx = tid; idx < 64 * 16; idx += 256) {
        int r = idx >> 4, c4 = (idx & 15) * 4;
        float4 v = *(const float4*)(g_qkv + (size_t)(b * LSEQ + l0 + r) * QKV_LD + h * DH + c4);
        *(float4*)(sQ + r * KV_STRIDE + c4) = v;
    }
    for (int idx = tid; idx < 127 * 16; idx += 256) {
        int r = idx >> 4, c4 = (idx & 15) * 4;
        int p = l0 + r;
        const float *ks, *vs;
        if (p < WWIN - 1) {
            ks = last_k + (size_t)(p * NH + h) * DH + c4;
            vs = last_v + (size_t)(p * NH + h) * DH + c4;
        } else {
            int pos = p - (WWIN - 1);
            const float* base = g_qkv + (size_t)(b * LSEQ + pos) * QKV_LD + h * DH + c4;
            ks = base + DMODEL;
            vs = base + 2 * DMODEL;
        }
        *(float4*)(sK + r * KV_STRIDE + c4) = *(const float4*)ks;
        *(float4*)(sV + r * KV_STRIDE + c4) = *(const float4*)vs;
    }
    __syncthreads();

    const int q   = tid >> 2;
    const int sub = tid & 3;

    float qreg[64];
    #pragma unroll
    for (int c4 = 0; c4 < 64; c4 += 4) {
        float4 v = *(const float4*)(sQ + q * KV_STRIDE + c4);
        qreg[c4 + 0] = v.x; qreg[c4 + 1] = v.y; qreg[c4 + 2] = v.z; qreg[c4 + 3] = v.w;
    }

    float sreg[16];
    #pragma unroll 4
    for (int i = 0; i < 16; i++) {
        int w = sub + i * 4;
        const float* kr = sK + (q + w) * KV_STRIDE;
        float acc = 0.0f;
        #pragma unroll
        for (int c4 = 0; c4 < 64; c4 += 4) {
            float4 kv = *(const float4*)(kr + c4);
            acc += qreg[c4 + 0] * kv.x + qreg[c4 + 1] * kv.y
                 + qreg[c4 + 2] * kv.z + qreg[c4 + 3] * kv.w;
        }
        sreg[i] = acc * 0.125f;
    }

    float m = sreg[0];
    #pragma unroll
    for (int i = 1; i < 16; i++) m = fmaxf(m, sreg[i]);
    m = fmaxf(m, __shfl_xor_sync(0xFFFFFFFFu, m, 1));
    m = fmaxf(m, __shfl_xor_sync(0xFFFFFFFFu, m, 2));
    float ssum = 0.0f;
    #pragma unroll
    for (int i = 0; i < 16; i++) { float e = __expf(sreg[i] - m); sreg[i] = e; ssum += e; }
    ssum += __shfl_xor_sync(0xFFFFFFFFu, ssum, 1);
    ssum += __shfl_xor_sync(0xFFFFFFFFu, ssum, 2);
    const float inv = 1.0f / ssum;
    #pragma unroll
    for (int i = 0; i < 16; i++) sS[q * S_STRIDE + sub + i * 4] = sreg[i] * inv;
    __syncthreads();

    float acc[16];
    #pragma unroll
    for (int j = 0; j < 16; j++) acc[j] = 0.0f;

    for (int w = 0; w < 64; w++) {
        float p = sS[q * S_STRIDE + w];
        const float* vr = sV + (q + w) * KV_STRIDE + sub * 16;
        #pragma unroll
        for (int c4 = 0; c4 < 16; c4 += 4) {
            float4 vv = *(const float4*)(vr + c4);
            acc[c4 + 0] += p * vv.x; acc[c4 + 1] += p * vv.y;
            acc[c4 + 2] += p * vv.z; acc[c4 + 3] += p * vv.w;
        }
    }

    float* outp = g_attr + (size_t)(b * LSEQ + l0 + q) * DMODEL + h * DH + sub * 16;
    #pragma unroll
    for (int c4 = 0; c4 < 16; c4 += 4)
        *(float4*)(outp + c4) = make_float4(tf32_round(acc[c4]),     tf32_round(acc[c4 + 1]),
                                            tf32_round(acc[c4 + 2]), tf32_round(acc[c4 + 3]));
}

// ---------------------------------------------------------------------------
// Launch
// ---------------------------------------------------------------------------
extern "C" void kernel_launch(void* const* d_in, const int* in_sizes, int n_in,
                              void* d_out, int out_size)
{
    const float* x      = (const float*)d_in[0];
    const float* Wq     = (const float*)d_in[1];
    const float* Wk     = (const float*)d_in[2];
    const float* Wv     = (const float*)d_in[3];
    const float* Wo     = (const float*)d_in[4];
    const float* last_k = (const float*)d_in[5];
    const float* last_v = (const float*)d_in[6];
    float* out = (float*)d_out;

    float *pxr, *pwr, *pwor, *pattr, *pqkv;
    cudaGetSymbolAddress((void**)&pxr,   g_xr);
    cudaGetSymbolAddress((void**)&pwr,   g_wr);
    cudaGetSymbolAddress((void**)&pwor,  g_wor);
    cudaGetSymbolAddress((void**)&pattr, g_attr);
    cudaGetSymbolAddress((void**)&pqkv,  g_qkv);

    cudaFuncSetAttribute(gemm_tf32_kernel, cudaFuncAttributeMaxDynamicSharedMemorySize,
                         GEMM_SMEM_BYTES);
    const int attn_smem = (127 * KV_STRIDE * 2 + 64 * KV_STRIDE + 64 * S_STRIDE) * (int)sizeof(float);
    cudaFuncSetAttribute(band_attn_kernel, cudaFuncAttributeMaxDynamicSharedMemorySize, attn_smem);

    // 1) tf32-round inputs
    round_kernel<<<(MTOT * DMODEL / 4 + 255) / 256, 256>>>(x, pxr, MTOT * DMODEL / 4);
    round_w3_kernel<<<(3 * DMODEL * DMODEL / 4 + 255) / 256, 256>>>(Wq, Wk, Wv, pwr);
    round_kernel<<<(DMODEL * DMODEL / 4 + 255) / 256, 256>>>(Wo, pwor, DMODEL * DMODEL / 4);

    // 2) fused QKV: g_qkv[2048][3072] = xr @ wr^T
    {
        dim3 g(3 * DMODEL / 128, MTOT / 128);
        gemm_tf32_kernel<<<g, 128, GEMM_SMEM_BYTES>>>(pxr, pwr, pqkv, 3 * DMODEL);
    }

    // 3) band attention -> g_attr (tf32-rounded in epilogue)
    {
        dim3 g(LSEQ / 64, NH, BSZ);
        band_attn_kernel<<<g, 256, attn_smem>>>(last_k, last_v);
    }

    // 4) out = attr @ wor^T
    {
        dim3 g(DMODEL / 128, MTOT / 128);
        gemm_tf32_kernel<<<g, 128, GEMM_SMEM_BYTES>>>(pattr, pwor, out, DMODEL);
    }
}

// round 10
// speedup vs baseline: 1.1485x; 1.1485x over previous
#include <cuda_runtime.h>
#include <cuda_bf16.h>
#include <cstdint>

// Problem constants
#define BSZ    2
#define LSEQ   1024
#define DMODEL 1024
#define NH     16
#define DH     64
#define WWIN   64
#define MTOT   (BSZ * LSEQ)      // 2048

// ---------------------------------------------------------------------------
// Scratch (device globals — no allocation allowed)
// ---------------------------------------------------------------------------
__device__ float g_xr  [MTOT * DMODEL];         // x rounded to tf32
__device__ float g_wr  [3 * DMODEL * DMODEL];   // Wq|Wk|Wv rows stacked, tf32-rounded
__device__ float g_wor [DMODEL * DMODEL];       // Wo tf32-rounded
__device__ float g_attr[MTOT * DMODEL];         // attention out, tf32-rounded
__device__ float g_qkv [MTOT * 3 * DMODEL];     // q|k|v f32, row-concat

// ---------------------------------------------------------------------------
// helpers
// ---------------------------------------------------------------------------
__device__ __forceinline__ uint32_t smem_u32(const void* p) {
    uint32_t a;
    asm("{ .reg .u64 t; cvta.to.shared.u64 t, %1; cvt.u32.u64 %0, t; }" : "=r"(a) : "l"(p));
    return a;
}
__device__ __forceinline__ float tf32_round(float v) {
    uint32_t o;
    asm("cvt.rna.tf32.f32 %0, %1;" : "=r"(o) : "f"(v));
    return __uint_as_float(o);
}
#define CP_ASYNC16(dst, src) \
    asm volatile("cp.async.cg.shared.global [%0], [%1], 16;" :: "r"(dst), "l"(src) : "memory")
#define CP_ASYNC_COMMIT() asm volatile("cp.async.commit_group;" ::: "memory")
#define CP_ASYNC_WAIT(n)  asm volatile("cp.async.wait_group %0;" :: "n"(n) : "memory")

__device__ __forceinline__ void mma_tf32(float* c, uint32_t a0, uint32_t a1,
                                         uint32_t a2, uint32_t a3,
                                         uint32_t b0, uint32_t b1) {
    asm volatile(
        "mma.sync.aligned.m16n8k8.row.col.f32.tf32.tf32.f32 "
        "{%0,%1,%2,%3}, {%4,%5,%6,%7}, {%8,%9}, {%0,%1,%2,%3};"
        : "+f"(c[0]), "+f"(c[1]), "+f"(c[2]), "+f"(c[3])
        : "r"(a0), "r"(a1), "r"(a2), "r"(a3), "r"(b0), "r"(b1));
}
__device__ __forceinline__ void ldsm4(uint32_t& r0, uint32_t& r1, uint32_t& r2,
                                      uint32_t& r3, uint32_t addr) {
    asm volatile("ldmatrix.sync.aligned.m8n8.x4.shared.b16 {%0,%1,%2,%3}, [%4];"
                 : "=r"(r0), "=r"(r1), "=r"(r2), "=r"(r3) : "r"(addr));
}

// ---------------------------------------------------------------------------
// TF32 tensor-core GEMM (R7 config): C[M][Ntot] = A[M][1024] @ B[Ntot][1024]^T
// CTA 128x128, BK=32, 8 warps (64x32 warp tiles), 3-stage cp.async pipeline,
// ldmatrix fragment loads. 2 CTAs/SM.
// ---------------------------------------------------------------------------
#define BK 32
#define NST (DMODEL / BK)             // 32 stages
#define SROW 36                       // padded row, words
#define TILE_WORDS (128 * SROW)
#define TILE_BYTES (TILE_WORDS * 4)
#define STAGE_WORDS (2 * TILE_WORDS)
#define STAGE_BYTES (STAGE_WORDS * 4)
#define GEMM_SMEM_BYTES (3 * STAGE_BYTES)  // 110592

__global__ __launch_bounds__(256, 2) void gemm_tf32_kernel(
    const float* __restrict__ A, const float* __restrict__ B,
    float* __restrict__ C, int Ntot)
{
    extern __shared__ float smem[];
    const int tid  = threadIdx.x;
    const int wid  = tid >> 5;
    const int lane = tid & 31;
    const int bn = blockIdx.x * 128;
    const int bm = blockIdx.y * 128;

    const int wm = (wid & 1) * 64;
    const int wn = (wid >> 1) * 32;
    const int qr = lane >> 2;
    const int qc = lane & 3;

    const uint32_t smem_base = smem_u32(smem);
    const float* gA = A + (size_t)bm * DMODEL;
    const float* gB = B + (size_t)bn * DMODEL;

    const int a_row = ((lane >> 3) & 1) * 8 + (lane & 7);
    const int a_ko  = (lane >> 4) * 4;
    uint32_t offA[4];
    #pragma unroll
    for (int mi = 0; mi < 4; mi++)
        offA[mi] = (uint32_t)(((wm + mi * 16 + a_row) * SROW + a_ko) * 4);
    const int b_row = (lane >> 4) * 8 + (lane & 7);
    const int b_ko  = ((lane >> 3) & 1) * 4;
    uint32_t offB[2];
    #pragma unroll
    for (int p = 0; p < 2; p++)
        offB[p] = (uint32_t)(TILE_BYTES + ((wn + p * 16 + b_row) * SROW + b_ko) * 4);

    auto load_stage = [&](int s) {
        uint32_t dst = smem_base + (uint32_t)(s % 3) * STAGE_BYTES;
        uint32_t dstB = dst + TILE_BYTES;
        const float* pA = gA + s * BK;
        const float* pB = gB + s * BK;
        #pragma unroll
        for (int i = 0; i < 4; i++) {
            int id = tid + i * 256;
            int row = id >> 3;
            int ch  = id & 7;
            uint32_t so = (uint32_t)(row * SROW + ch * 4) * 4;
            CP_ASYNC16(dst  + so, pA + (size_t)row * DMODEL + ch * 4);
            CP_ASYNC16(dstB + so, pB + (size_t)row * DMODEL + ch * 4);
        }
    };

    float acc[4][4][4];
    #pragma unroll
    for (int mi = 0; mi < 4; mi++)
        #pragma unroll
        for (int ni = 0; ni < 4; ni++)
            #pragma unroll
            for (int j = 0; j < 4; j++) acc[mi][ni][j] = 0.0f;

    load_stage(0); CP_ASYNC_COMMIT();
    load_stage(1); CP_ASYNC_COMMIT();

    for (int s = 0; s < NST; s++) {
        CP_ASYNC_WAIT(1);
        __syncthreads();
        if (s + 2 < NST) load_stage(s + 2);
        CP_ASYNC_COMMIT();

        const uint32_t stage = smem_base + (uint32_t)(s % 3) * STAGE_BYTES;

        #pragma unroll
        for (int ks = 0; ks < 4; ks++) {
            const uint32_t kb = (uint32_t)(ks * 32);
            uint32_t af[4][4];
            #pragma unroll
            for (int mi = 0; mi < 4; mi++)
                ldsm4(af[mi][0], af[mi][1], af[mi][2], af[mi][3], stage + offA[mi] + kb);
            uint32_t bf[4][2];
            #pragma unroll
            for (int p = 0; p < 2; p++)
                ldsm4(bf[2*p][0], bf[2*p][1], bf[2*p+1][0], bf[2*p+1][1],
                      stage + offB[p] + kb);
            #pragma unroll
            for (int mi = 0; mi < 4; mi++)
                #pragma unroll
                for (int ni = 0; ni < 4; ni++)
                    mma_tf32(acc[mi][ni], af[mi][0], af[mi][1], af[mi][2], af[mi][3],
                             bf[ni][0], bf[ni][1]);
        }
    }

    #pragma unroll
    for (int mi = 0; mi < 4; mi++) {
        const int row = bm + wm + mi * 16 + qr;
        #pragma unroll
        for (int ni = 0; ni < 4; ni++) {
            const int col = bn + wn + ni * 8 + qc * 2;
            float* p0 = C + (size_t)row * Ntot + col;
            float* p1 = p0 + (size_t)8 * Ntot;
            *(float2*)p0 = make_float2(acc[mi][ni][0], acc[mi][ni][1]);
            *(float2*)p1 = make_float2(acc[mi][ni][2], acc[mi][ni][3]);
        }
    }
}

// ---------------------------------------------------------------------------
// Fused tf32 rounding prepass: x -> g_xr, Wq|Wk|Wv -> g_wr, Wo -> g_wor
// ---------------------------------------------------------------------------
#define XN4 (MTOT * DMODEL / 4)          // 524288
#define WN4 (DMODEL * DMODEL / 4)        // 262144
#define RN4 (XN4 + 4 * WN4)              // 1572864

__global__ __launch_bounds__(256) void round_all_kernel(
    const float* __restrict__ x,  const float* __restrict__ Wq,
    const float* __restrict__ Wk, const float* __restrict__ Wv,
    const float* __restrict__ Wo,
    float* __restrict__ xr, float* __restrict__ wr, float* __restrict__ wor)
{
    int i = blockIdx.x * 256 + threadIdx.x;
    if (i >= RN4) return;
    const float4* src; float4* dst; int off;
    if (i < XN4)               { src = (const float4*)x;  dst = (float4*)xr;            off = i; }
    else if (i < XN4 + WN4)    { src = (const float4*)Wq; dst = (float4*)wr;            off = i - XN4; }
    else if (i < XN4 + 2*WN4)  { src = (const float4*)Wk; dst = (float4*)wr + WN4;      off = i - XN4 - WN4; }
    else if (i < XN4 + 3*WN4)  { src = (const float4*)Wv; dst = (float4*)wr + 2*WN4;    off = i - XN4 - 2*WN4; }
    else                       { src = (const float4*)Wo; dst = (float4*)wor;           off = i - XN4 - 3*WN4; }
    float4 v = src[off];
    v.x = tf32_round(v.x); v.y = tf32_round(v.y);
    v.z = tf32_round(v.z); v.w = tf32_round(v.w);
    dst[off] = v;
}

// ---------------------------------------------------------------------------
// Band attention (fp32 math, shuffle softmax, shfl-broadcast AV — no P smem).
// Reads q|k|v from g_qkv; writes tf32-rounded output to g_attr.
// One __syncthreads total.
// ---------------------------------------------------------------------------
#define KV_STRIDE 68
#define QKV_LD    (3 * DMODEL)
#define ATTN_SMEM_BYTES ((127 * KV_STRIDE * 2 + 64 * KV_STRIDE) * 4)  // 86496

__global__ __launch_bounds__(256, 2) void band_attn_kernel(
    const float* __restrict__ last_k, const float* __restrict__ last_v)
{
    extern __shared__ float smem[];
    float* sK = smem;
    float* sV = sK + 127 * KV_STRIDE;
    float* sQ = sV + 127 * KV_STRIDE;

    const int l0 = blockIdx.x * 64;
    const int h  = blockIdx.y;
    const int b  = blockIdx.z;
    const int tid = threadIdx.x;

    for (int idx = tid; idx < 64 * 16; idx += 256) {
        int r = idx >> 4, c4 = (idx & 15) * 4;
        float4 v = *(const float4*)(g_qkv + (size_t)(b * LSEQ + l0 + r) * QKV_LD + h * DH + c4);
        *(float4*)(sQ + r * KV_STRIDE + c4) = v;
    }
    for (int idx = tid; idx < 127 * 16; idx += 256) {
        int r = idx >> 4, c4 = (idx & 15) * 4;
        int p = l0 + r;
        const float *ks, *vs;
        if (p < WWIN - 1) {
            ks = last_k + (size_t)(p * NH + h) * DH + c4;
            vs = last_v + (size_t)(p * NH + h) * DH + c4;
        } else {
            int pos = p - (WWIN - 1);
            const float* base = g_qkv + (size_t)(b * LSEQ + pos) * QKV_LD + h * DH + c4;
            ks = base + DMODEL;
            vs = base + 2 * DMODEL;
        }
        *(float4*)(sK + r * KV_STRIDE + c4) = *(const float4*)ks;
        *(float4*)(sV + r * KV_STRIDE + c4) = *(const float4*)vs;
    }
    __syncthreads();

    const int q   = tid >> 2;
    const int sub = tid & 3;
    const int qlane = (q & 7) << 2;   // base lane of this quad within its warp

    float qreg[64];
    #pragma unroll
    for (int c4 = 0; c4 < 64; c4 += 4) {
        float4 v = *(const float4*)(sQ + q * KV_STRIDE + c4);
        qreg[c4 + 0] = v.x; qreg[c4 + 1] = v.y; qreg[c4 + 2] = v.z; qreg[c4 + 3] = v.w;
    }

    // scores in registers: thread covers w = sub, sub+4, ..., sub+60
    float sreg[16];
    #pragma unroll 4
    for (int i = 0; i < 16; i++) {
        int w = sub + i * 4;
        const float* kr = sK + (q + w) * KV_STRIDE;
        float acc = 0.0f;
        #pragma unroll
        for (int c4 = 0; c4 < 64; c4 += 4) {
            float4 kv = *(const float4*)(kr + c4);
            acc += qreg[c4 + 0] * kv.x + qreg[c4 + 1] * kv.y
                 + qreg[c4 + 2] * kv.z + qreg[c4 + 3] * kv.w;
        }
        sreg[i] = acc * 0.125f;
    }

    // quad-shuffle softmax (lanes qlane..qlane+3 hold the 64 scores of query q)
    float m = sreg[0];
    #pragma unroll
    for (int i = 1; i < 16; i++) m = fmaxf(m, sreg[i]);
    m = fmaxf(m, __shfl_xor_sync(0xFFFFFFFFu, m, 1));
    m = fmaxf(m, __shfl_xor_sync(0xFFFFFFFFu, m, 2));
    float ssum = 0.0f;
    #pragma unroll
    for (int i = 0; i < 16; i++) { float e = __expf(sreg[i] - m); sreg[i] = e; ssum += e; }
    ssum += __shfl_xor_sync(0xFFFFFFFFu, ssum, 1);
    ssum += __shfl_xor_sync(0xFFFFFFFFu, ssum, 2);
    const float inv = 1.0f / ssum;
    #pragma unroll
    for (int i = 0; i < 16; i++) sreg[i] *= inv;   // normalized P in registers

    // AV: thread handles dims [sub*16, sub*16+16) for its query.
    // P[w] broadcast from quad lane holding it (w = 4*i + j -> lane qlane+j, sreg[i]).
    float acc[16];
    #pragma unroll
    for (int j = 0; j < 16; j++) acc[j] = 0.0f;

    #pragma unroll
    for (int i = 0; i < 16; i++) {
        #pragma unroll
        for (int j = 0; j < 4; j++) {
            const int w = i * 4 + j;
            const float p = __shfl_sync(0xFFFFFFFFu, sreg[i], qlane + j);
            const float* vr = sV + (q + w) * KV_STRIDE + sub * 16;
            #pragma unroll
            for (int c4 = 0; c4 < 16; c4 += 4) {
                float4 vv = *(const float4*)(vr + c4);
                acc[c4 + 0] += p * vv.x; acc[c4 + 1] += p * vv.y;
                acc[c4 + 2] += p * vv.z; acc[c4 + 3] += p * vv.w;
            }
        }
    }

    // store tf32-rounded (feeds the out-projection GEMM directly)
    float* outp = g_attr + (size_t)(b * LSEQ + l0 + q) * DMODEL + h * DH + sub * 16;
    #pragma unroll
    for (int c4 = 0; c4 < 16; c4 += 4)
        *(float4*)(outp + c4) = make_float4(tf32_round(acc[c4]),     tf32_round(acc[c4 + 1]),
                                            tf32_round(acc[c4 + 2]), tf32_round(acc[c4 + 3]));
}

// ---------------------------------------------------------------------------
// Launch
// ---------------------------------------------------------------------------
extern "C" void kernel_launch(void* const* d_in, const int* in_sizes, int n_in,
                              void* d_out, int out_size)
{
    const float* x      = (const float*)d_in[0];
    const float* Wq     = (const float*)d_in[1];
    const float* Wk     = (const float*)d_in[2];
    const float* Wv     = (const float*)d_in[3];
    const float* Wo     = (const float*)d_in[4];
    const float* last_k = (const float*)d_in[5];
    const float* last_v = (const float*)d_in[6];
    float* out = (float*)d_out;

    float *pxr, *pwr, *pwor, *pattr, *pqkv;
    cudaGetSymbolAddress((void**)&pxr,   g_xr);
    cudaGetSymbolAddress((void**)&pwr,   g_wr);
    cudaGetSymbolAddress((void**)&pwor,  g_wor);
    cudaGetSymbolAddress((void**)&pattr, g_attr);
    cudaGetSymbolAddress((void**)&pqkv,  g_qkv);

    cudaFuncSetAttribute(gemm_tf32_kernel, cudaFuncAttributeMaxDynamicSharedMemorySize,
                         GEMM_SMEM_BYTES);
    cudaFuncSetAttribute(band_attn_kernel, cudaFuncAttributeMaxDynamicSharedMemorySize,
                         ATTN_SMEM_BYTES);

    // 1) fused tf32-round of all inputs (one launch)
    round_all_kernel<<<(RN4 + 255) / 256, 256>>>(x, Wq, Wk, Wv, Wo, pxr, pwr, pwor);

    // 2) fused QKV: g_qkv[2048][3072] = xr @ wr^T
    {
        dim3 g(3 * DMODEL / 128, MTOT / 128);
        gemm_tf32_kernel<<<g, 256, GEMM_SMEM_BYTES>>>(pxr, pwr, pqkv, 3 * DMODEL);
    }

    // 3) band attention -> g_attr (tf32-rounded in epilogue)
    {
        dim3 g(LSEQ / 64, NH, BSZ);
        band_attn_kernel<<<g, 256, ATTN_SMEM_BYTES>>>(last_k, last_v);
    }

    // 4) out = attr @ wor^T
    {
        dim3 g(DMODEL / 128, MTOT / 128);
        gemm_tf32_kernel<<<g, 256, GEMM_SMEM_BYTES>>>(pattr, pwor, out, DMODEL);
    }
}

// round 12
// speedup vs baseline: 1.2015x; 1.0462x over previous
#include <cuda_runtime.h>
#include <cuda_bf16.h>
#include <cstdint>

// Problem constants
#define BSZ    2
#define LSEQ   1024
#define DMODEL 1024
#define NH     16
#define DH     64
#define WWIN   64
#define MTOT   (BSZ * LSEQ)      // 2048

// ---------------------------------------------------------------------------
// Scratch (device globals — no allocation allowed)
// ---------------------------------------------------------------------------
__device__ float g_xr  [MTOT * DMODEL];         // x rounded to tf32
__device__ float g_wr  [3 * DMODEL * DMODEL];   // Wq|Wk|Wv rows stacked, tf32-rounded
__device__ float g_wor [DMODEL * DMODEL];       // Wo tf32-rounded
__device__ float g_attr[MTOT * DMODEL];         // attention out, tf32-rounded
__device__ float g_qkv [MTOT * 3 * DMODEL];     // q|k|v f32, row-concat

// ---------------------------------------------------------------------------
// helpers
// ---------------------------------------------------------------------------
__device__ __forceinline__ uint32_t smem_u32(const void* p) {
    uint32_t a;
    asm("{ .reg .u64 t; cvta.to.shared.u64 t, %1; cvt.u32.u64 %0, t; }" : "=r"(a) : "l"(p));
    return a;
}
__device__ __forceinline__ float tf32_round(float v) {
    uint32_t o;
    asm("cvt.rna.tf32.f32 %0, %1;" : "=r"(o) : "f"(v));
    return __uint_as_float(o);
}
#define CP_ASYNC16(dst, src) \
    asm volatile("cp.async.cg.shared.global [%0], [%1], 16;" :: "r"(dst), "l"(src) : "memory")
#define CP_ASYNC_COMMIT() asm volatile("cp.async.commit_group;" ::: "memory")
#define CP_ASYNC_WAIT(n)  asm volatile("cp.async.wait_group %0;" :: "n"(n) : "memory")

__device__ __forceinline__ void mma_tf32(float* c, uint32_t a0, uint32_t a1,
                                         uint32_t a2, uint32_t a3,
                                         uint32_t b0, uint32_t b1) {
    asm volatile(
        "mma.sync.aligned.m16n8k8.row.col.f32.tf32.tf32.f32 "
        "{%0,%1,%2,%3}, {%4,%5,%6,%7}, {%8,%9}, {%0,%1,%2,%3};"
        : "+f"(c[0]), "+f"(c[1]), "+f"(c[2]), "+f"(c[3])
        : "r"(a0), "r"(a1), "r"(a2), "r"(a3), "r"(b0), "r"(b1));
}
__device__ __forceinline__ void ldsm4(uint32_t& r0, uint32_t& r1, uint32_t& r2,
                                      uint32_t& r3, uint32_t addr) {
    asm volatile("ldmatrix.sync.aligned.m8n8.x4.shared.b16 {%0,%1,%2,%3}, [%4];"
                 : "=r"(r0), "=r"(r1), "=r"(r2), "=r"(r3) : "r"(addr));
}

// ---------------------------------------------------------------------------
// TF32 tensor-core GEMM (R7 config): C[M][Ntot] = A[M][1024] @ B[Ntot][1024]^T
// CTA 128x128, BK=32, 8 warps (64x32 warp tiles), 3-stage cp.async pipeline,
// ldmatrix fragment loads. 2 CTAs/SM.
// ---------------------------------------------------------------------------
#define BK 32
#define NST (DMODEL / BK)             // 32 stages
#define SROW 36                       // padded row, words
#define TILE_WORDS (128 * SROW)
#define TILE_BYTES (TILE_WORDS * 4)
#define STAGE_WORDS (2 * TILE_WORDS)
#define STAGE_BYTES (STAGE_WORDS * 4)
#define GEMM_SMEM_BYTES (3 * STAGE_BYTES)  // 110592

__global__ __launch_bounds__(256, 2) void gemm_tf32_kernel(
    const float* __restrict__ A, const float* __restrict__ B,
    float* __restrict__ C, int Ntot)
{
    extern __shared__ float smem[];
    const int tid  = threadIdx.x;
    const int wid  = tid >> 5;
    const int lane = tid & 31;
    const int bn = blockIdx.x * 128;
    const int bm = blockIdx.y * 128;

    const int wm = (wid & 1) * 64;
    const int wn = (wid >> 1) * 32;
    const int qr = lane >> 2;
    const int qc = lane & 3;

    const uint32_t smem_base = smem_u32(smem);
    const float* gA = A + (size_t)bm * DMODEL;
    const float* gB = B + (size_t)bn * DMODEL;

    const int a_row = ((lane >> 3) & 1) * 8 + (lane & 7);
    const int a_ko  = (lane >> 4) * 4;
    uint32_t offA[4];
    #pragma unroll
    for (int mi = 0; mi < 4; mi++)
        offA[mi] = (uint32_t)(((wm + mi * 16 + a_row) * SROW + a_ko) * 4);
    const int b_row = (lane >> 4) * 8 + (lane & 7);
    const int b_ko  = ((lane >> 3) & 1) * 4;
    uint32_t offB[2];
    #pragma unroll
    for (int p = 0; p < 2; p++)
        offB[p] = (uint32_t)(TILE_BYTES + ((wn + p * 16 + b_row) * SROW + b_ko) * 4);

    auto load_stage = [&](int s) {
        uint32_t dst = smem_base + (uint32_t)(s % 3) * STAGE_BYTES;
        uint32_t dstB = dst + TILE_BYTES;
        const float* pA = gA + s * BK;
        const float* pB = gB + s * BK;
        #pragma unroll
        for (int i = 0; i < 4; i++) {
            int id = tid + i * 256;
            int row = id >> 3;
            int ch  = id & 7;
            uint32_t so = (uint32_t)(row * SROW + ch * 4) * 4;
            CP_ASYNC16(dst  + so, pA + (size_t)row * DMODEL + ch * 4);
            CP_ASYNC16(dstB + so, pB + (size_t)row * DMODEL + ch * 4);
        }
    };

    float acc[4][4][4];
    #pragma unroll
    for (int mi = 0; mi < 4; mi++)
        #pragma unroll
        for (int ni = 0; ni < 4; ni++)
            #pragma unroll
            for (int j = 0; j < 4; j++) acc[mi][ni][j] = 0.0f;

    load_stage(0); CP_ASYNC_COMMIT();
    load_stage(1); CP_ASYNC_COMMIT();

    for (int s = 0; s < NST; s++) {
        CP_ASYNC_WAIT(1);
        __syncthreads();
        if (s + 2 < NST) load_stage(s + 2);
        CP_ASYNC_COMMIT();

        const uint32_t stage = smem_base + (uint32_t)(s % 3) * STAGE_BYTES;

        #pragma unroll
        for (int ks = 0; ks < 4; ks++) {
            const uint32_t kb = (uint32_t)(ks * 32);
            uint32_t af[4][4];
            #pragma unroll
            for (int mi = 0; mi < 4; mi++)
                ldsm4(af[mi][0], af[mi][1], af[mi][2], af[mi][3], stage + offA[mi] + kb);
            uint32_t bf[4][2];
            #pragma unroll
            for (int p = 0; p < 2; p++)
                ldsm4(bf[2*p][0], bf[2*p][1], bf[2*p+1][0], bf[2*p+1][1],
                      stage + offB[p] + kb);
            #pragma unroll
            for (int mi = 0; mi < 4; mi++)
                #pragma unroll
                for (int ni = 0; ni < 4; ni++)
                    mma_tf32(acc[mi][ni], af[mi][0], af[mi][1], af[mi][2], af[mi][3],
                             bf[ni][0], bf[ni][1]);
        }
    }

    #pragma unroll
    for (int mi = 0; mi < 4; mi++) {
        const int row = bm + wm + mi * 16 + qr;
        #pragma unroll
        for (int ni = 0; ni < 4; ni++) {
            const int col = bn + wn + ni * 8 + qc * 2;
            float* p0 = C + (size_t)row * Ntot + col;
            float* p1 = p0 + (size_t)8 * Ntot;
            *(float2*)p0 = make_float2(acc[mi][ni][0], acc[mi][ni][1]);
            *(float2*)p1 = make_float2(acc[mi][ni][2], acc[mi][ni][3]);
        }
    }
}

// ---------------------------------------------------------------------------
// Fused tf32 rounding prepass: x -> g_xr, Wq|Wk|Wv -> g_wr, Wo -> g_wor
// ---------------------------------------------------------------------------
#define XN4 (MTOT * DMODEL / 4)          // 524288
#define WN4 (DMODEL * DMODEL / 4)        // 262144
#define RN4 (XN4 + 4 * WN4)              // 1572864

__global__ __launch_bounds__(256) void round_all_kernel(
    const float* __restrict__ x,  const float* __restrict__ Wq,
    const float* __restrict__ Wk, const float* __restrict__ Wv,
    const float* __restrict__ Wo,
    float* __restrict__ xr, float* __restrict__ wr, float* __restrict__ wor)
{
    int i = blockIdx.x * 256 + threadIdx.x;
    if (i >= RN4) return;
    const float4* src; float4* dst; int off;
    if (i < XN4)               { src = (const float4*)x;  dst = (float4*)xr;            off = i; }
    else if (i < XN4 + WN4)    { src = (const float4*)Wq; dst = (float4*)wr;            off = i - XN4; }
    else if (i < XN4 + 2*WN4)  { src = (const float4*)Wk; dst = (float4*)wr + WN4;      off = i - XN4 - WN4; }
    else if (i < XN4 + 3*WN4)  { src = (const float4*)Wv; dst = (float4*)wr + 2*WN4;    off = i - XN4 - 2*WN4; }
    else                       { src = (const float4*)Wo; dst = (float4*)wor;           off = i - XN4 - 3*WN4; }
    float4 v = src[off];
    v.x = tf32_round(v.x); v.y = tf32_round(v.y);
    v.z = tf32_round(v.z); v.w = tf32_round(v.w);
    dst[off] = v;
}

// ---------------------------------------------------------------------------
// Band attention: MMA scores + SIMT shuffle softmax + shfl-broadcast AV.
//   S[64][128] = Qtile(64x64) @ Kwin(128x64)^T   (tf32 MMA, ldmatrix)
//   softmax over the 64-wide band (registers, quad shuffles)  [as R10]
//   AV via shfl-broadcast P against fp32 V rows               [as R10]
// smem: Q 64x68 | K 128x68 (aliased by S 64x136 after scores) | V 127x68
// ---------------------------------------------------------------------------
#define QS 68         // Q/K row stride (words); 68*4=272 B, 16B-aligned
#define SS 136        // S row stride (words);  136*4=544 B, 16B-aligned
#define KV_STRIDE 68
#define QKV_LD (3 * DMODEL)
#define ATTN_Q_WORDS (64 * QS)      // 4352
#define ATTN_K_WORDS (128 * QS)     // 8704  (== 64*SS exactly)
#define ATTN_V_WORDS (127 * KV_STRIDE)
#define ATTN_SMEM_BYTES ((ATTN_Q_WORDS + ATTN_K_WORDS + ATTN_V_WORDS) * 4)  // 86768

__global__ __launch_bounds__(256, 2) void band_attn_kernel(
    const float* __restrict__ last_k, const float* __restrict__ last_v)
{
    extern __shared__ float smem[];
    float* sQ = smem;                     // 64 x QS
    float* sK = smem + ATTN_Q_WORDS;      // 128 x QS ; aliased as S (64 x SS)
    float* sV = sK + ATTN_K_WORDS;        // 127 x KV_STRIDE

    const int l0 = blockIdx.x * 64;
    const int h  = blockIdx.y;
    const int b  = blockIdx.z;
    const int tid = threadIdx.x;
    const int wid = tid >> 5;
    const int lane = tid & 31;

    // ---- load Q (tf32-rounded, MMA operand) ----
    for (int idx = tid; idx < 64 * 16; idx += 256) {
        int r = idx >> 4, c4 = (idx & 15) * 4;
        float4 v = *(const float4*)(g_qkv + (size_t)(b * LSEQ + l0 + r) * QKV_LD + h * DH + c4);
        float* d = sQ + r * QS + c4;
        d[0] = tf32_round(v.x); d[1] = tf32_round(v.y);
        d[2] = tf32_round(v.z); d[3] = tf32_round(v.w);
    }
    // ---- load K window rows 0..127 (tf32-rounded; OOB -> 0) ----
    for (int idx = tid; idx < 128 * 16; idx += 256) {
        int r = idx >> 4, c4 = (idx & 15) * 4;
        int p = l0 + r;
        float4 v;
        if (p < WWIN - 1) {
            v = *(const float4*)(last_k + (size_t)(p * NH + h) * DH + c4);
        } else {
            int pos = p - (WWIN - 1);
            if (pos < LSEQ)
                v = *(const float4*)(g_qkv + (size_t)(b * LSEQ + pos) * QKV_LD + DMODEL + h * DH + c4);
            else
                v = make_float4(0.f, 0.f, 0.f, 0.f);
        }
        float* d = sK + r * QS + c4;
        d[0] = tf32_round(v.x); d[1] = tf32_round(v.y);
        d[2] = tf32_round(v.z); d[3] = tf32_round(v.w);
    }
    // ---- load V window rows 0..126 (fp32, SIMT AV operand) ----
    for (int idx = tid; idx < 127 * 16; idx += 256) {
        int r = idx >> 4, c4 = (idx & 15) * 4;
        int p = l0 + r;
        const float* vs;
        if (p < WWIN - 1) {
            vs = last_v + (size_t)(p * NH + h) * DH + c4;
        } else {
            int pos = p - (WWIN - 1);
            vs = g_qkv + (size_t)(b * LSEQ + pos) * QKV_LD + 2 * DMODEL + h * DH + c4;
        }
        *(float4*)(sV + r * KV_STRIDE + c4) = *(const float4*)vs;
    }
    __syncthreads();

    // ---- scores MMA: warp (mi = wid>>1) rows, (half = wid&1) col half ----
    const int mi   = wid >> 1;      // 0..3 -> S rows [16mi, 16mi+16)
    const int half = wid & 1;       // 0..1 -> S cols [64*half, 64*half+64)
    const int a_row = ((lane >> 3) & 1) * 8 + (lane & 7);
    const int a_ko  = (lane >> 4) * 4;
    const int b_row = (lane >> 4) * 8 + (lane & 7);
    const int b_ko  = ((lane >> 3) & 1) * 4;
    const int qr = lane >> 2;
    const int qc = lane & 3;

    float sacc[8][4];
    #pragma unroll
    for (int ni = 0; ni < 8; ni++)
        #pragma unroll
        for (int j = 0; j < 4; j++) sacc[ni][j] = 0.0f;

    {
        const uint32_t qoff = smem_u32(sQ) + (uint32_t)(((mi * 16 + a_row) * QS + a_ko) * 4);
        uint32_t koff[4];
        #pragma unroll
        for (int p4 = 0; p4 < 4; p4++)
            koff[p4] = smem_u32(sK) + (uint32_t)(((half * 64 + p4 * 16 + b_row) * QS + b_ko) * 4);

        #pragma unroll
        for (int k = 0; k < 8; k++) {
            const uint32_t kb = (uint32_t)(k * 32);   // 8 words per k-step
            uint32_t af[4];
            ldsm4(af[0], af[1], af[2], af[3], qoff + kb);
            uint32_t bf[8][2];
            #pragma unroll
            for (int p4 = 0; p4 < 4; p4++)
                ldsm4(bf[2*p4][0], bf[2*p4][1], bf[2*p4+1][0], bf[2*p4+1][1], koff[p4] + kb);
            #pragma unroll
            for (int ni = 0; ni < 8; ni++)
                mma_tf32(sacc[ni], af[0], af[1], af[2], af[3], bf[ni][0], bf[ni][1]);
        }
    }
    __syncthreads();   // all warps done reading K; region becomes S

    // ---- store S (raw scores; scale applied at softmax read) ----
    float* sS = sK;    // 64 x SS, exactly the K footprint
    #pragma unroll
    for (int ni = 0; ni < 8; ni++) {
        const int r0 = mi * 16 + qr;
        const int c0 = (half * 8 + ni) * 8 + qc * 2;
        sS[r0 * SS + c0]           = sacc[ni][0];
        sS[r0 * SS + c0 + 1]       = sacc[ni][1];
        sS[(r0 + 8) * SS + c0]     = sacc[ni][2];
        sS[(r0 + 8) * SS + c0 + 1] = sacc[ni][3];
    }
    __syncthreads();

    // ---- band softmax (registers, quad shuffles) — structure as R10 ----
    const int q   = tid >> 2;
    const int sub = tid & 3;
    const int qlane = (q & 7) << 2;

    float sreg[16];
    #pragma unroll
    for (int i = 0; i < 16; i++)
        sreg[i] = sS[q * SS + (q + sub + 4 * i)] * 0.125f;

    float m = sreg[0];
    #pragma unroll
    for (int i = 1; i < 16; i++) m = fmaxf(m, sreg[i]);
    m = fmaxf(m, __shfl_xor_sync(0xFFFFFFFFu, m, 1));
    m = fmaxf(m, __shfl_xor_sync(0xFFFFFFFFu, m, 2));
    float ssum = 0.0f;
    #pragma unroll
    for (int i = 0; i < 16; i++) { float e = __expf(sreg[i] - m); sreg[i] = e; ssum += e; }
    ssum += __shfl_xor_sync(0xFFFFFFFFu, ssum, 1);
    ssum += __shfl_xor_sync(0xFFFFFFFFu, ssum, 2);
    const float inv = 1.0f / ssum;
    #pragma unroll
    for (int i = 0; i < 16; i++) sreg[i] *= inv;

    // ---- AV: shfl-broadcast P, fp32 V (identical to R10) ----
    float acc[16];
    #pragma unroll
    for (int j = 0; j < 16; j++) acc[j] = 0.0f;

    #pragma unroll
    for (int i = 0; i < 16; i++) {
        #pragma unroll
        for (int j = 0; j < 4; j++) {
            const int w = i * 4 + j;
            const float p = __shfl_sync(0xFFFFFFFFu, sreg[i], qlane + j);
            const float* vr = sV + (q + w) * KV_STRIDE + sub * 16;
            #pragma unroll
            for (int c4 = 0; c4 < 16; c4 += 4) {
                float4 vv = *(const float4*)(vr + c4);
                acc[c4 + 0] += p * vv.x; acc[c4 + 1] += p * vv.y;
                acc[c4 + 2] += p * vv.z; acc[c4 + 3] += p * vv.w;
            }
        }
    }

    float* outp = g_attr + (size_t)(b * LSEQ + l0 + q) * DMODEL + h * DH + sub * 16;
    #pragma unroll
    for (int c4 = 0; c4 < 16; c4 += 4)
        *(float4*)(outp + c4) = make_float4(tf32_round(acc[c4]),     tf32_round(acc[c4 + 1]),
                                            tf32_round(acc[c4 + 2]), tf32_round(acc[c4 + 3]));
}

// ---------------------------------------------------------------------------
// Launch
// ---------------------------------------------------------------------------
extern "C" void kernel_launch(void* const* d_in, const int* in_sizes, int n_in,
                              void* d_out, int out_size)
{
    const float* x      = (const float*)d_in[0];
    const float* Wq     = (const float*)d_in[1];
    const float* Wk     = (const float*)d_in[2];
    const float* Wv     = (const float*)d_in[3];
    const float* Wo     = (const float*)d_in[4];
    const float* last_k = (const float*)d_in[5];
    const float* last_v = (const float*)d_in[6];
    float* out = (float*)d_out;

    float *pxr, *pwr, *pwor, *pattr, *pqkv;
    cudaGetSymbolAddress((void**)&pxr,   g_xr);
    cudaGetSymbolAddress((void**)&pwr,   g_wr);
    cudaGetSymbolAddress((void**)&pwor,  g_wor);
    cudaGetSymbolAddress((void**)&pattr, g_attr);
    cudaGetSymbolAddress((void**)&pqkv,  g_qkv);

    cudaFuncSetAttribute(gemm_tf32_kernel, cudaFuncAttributeMaxDynamicSharedMemorySize,
                         GEMM_SMEM_BYTES);
    cudaFuncSetAttribute(band_attn_kernel, cudaFuncAttributeMaxDynamicSharedMemorySize,
                         ATTN_SMEM_BYTES);

    // 1) fused tf32-round of all inputs (one launch)
    round_all_kernel<<<(RN4 + 255) / 256, 256>>>(x, Wq, Wk, Wv, Wo, pxr, pwr, pwor);

    // 2) fused QKV: g_qkv[2048][3072] = xr @ wr^T
    {
        dim3 g(3 * DMODEL / 128, MTOT / 128);
        gemm_tf32_kernel<<<g, 256, GEMM_SMEM_BYTES>>>(pxr, pwr, pqkv, 3 * DMODEL);
    }

    // 3) band attention (MMA scores) -> g_attr (tf32-rounded)
    {
        dim3 g(LSEQ / 64, NH, BSZ);
        band_attn_kernel<<<g, 256, ATTN_SMEM_BYTES>>>(last_k, last_v);
    }

    // 4) out = attr @ wor^T
    {
        dim3 g(DMODEL / 128, MTOT / 128);
        gemm_tf32_kernel<<<g, 256, GEMM_SMEM_BYTES>>>(pattr, pwor, out, DMODEL);
    }
}